// round 6
// baseline (speedup 1.0000x reference)
#include <cuda_runtime.h>
#include <math.h>

typedef unsigned long long ull;

#define T_STEPS 512
#define BATCH   64
#define INP     1024
#define HID     1024
#define GATES   4096
#define NBLK    128     // persistent blocks (1/SM, co-resident on 148 SMs)
#define NTHR    512     // 8 consumer warps + 8 producer warps

// Scratch (static device arrays — no allocation APIs allowed)
__device__ __align__(16) float g_G[(size_t)T_STEPS * BATCH * GATES];   // 512 MB
__device__ ull       g_bar_gen;   // grid barrier generation (monotonic)
__device__ unsigned  g_bar_cnt;   // grid barrier arrive counter

// ---- packed fp32x2 helpers (Blackwell FFMA2: 2 fp32 FMA per instr, bit-exact) ----
__device__ __forceinline__ ull pk2(float x, float y) {
    ull r; asm("mov.b64 %0, {%1, %2};" : "=l"(r) : "f"(x), "f"(y)); return r;
}
__device__ __forceinline__ ull dup2(float x) {
    ull r; asm("mov.b64 %0, {%1, %1};" : "=l"(r) : "f"(x)); return r;
}
__device__ __forceinline__ void fma2(ull& d, ull a, ull b) {
    asm("fma.rn.f32x2 %0, %1, %2, %0;" : "+l"(d) : "l"(a), "l"(b));
}
__device__ __forceinline__ float2 up2(ull v) {
    float2 f; asm("mov.b64 {%0, %1}, %2;" : "=f"(f.x), "=f"(f.y) : "l"(v)); return f;
}
__device__ __forceinline__ float sigf(float v) { return 1.0f / (1.0f + expf(-v)); }

#define BAR_SYNC_64(id) asm volatile("bar.sync %0, 64;" :: "r"(id) : "memory")

// ---------------------------------------------------------------------------
// Kernel 1: G = X @ W_ih^T + (b_ih + b_hh)
// M = 32768, N = 4096, K = 1024. 128x128 tile, BK=8, 256 thr, 8x8/thread (FFMA2).
// launch_bounds(256,2): cap regs so 2 blocks/SM co-reside (4 warps/SMSP).
// ---------------------------------------------------------------------------
__global__ __launch_bounds__(256, 2) void input_gemm_kernel(
    const float* __restrict__ X,
    const float* __restrict__ W,
    const float* __restrict__ b_ih,
    const float* __restrict__ b_hh)
{
    __shared__ __align__(16) float As[8][128];
    __shared__ __align__(16) float Bs[8][128];

    const int tid = threadIdx.x;
    const int n0  = blockIdx.x * 128;
    const int m0  = blockIdx.y * 128;
    const int tx  = tid & 15;
    const int ty  = tid >> 4;
    const int lrow = tid >> 1;
    const int lk4  = (tid & 1) * 4;

    ull acc2[8][4];
#pragma unroll
    for (int i = 0; i < 8; i++)
#pragma unroll
        for (int jp = 0; jp < 4; jp++) acc2[i][jp] = 0ULL;

    const float* Arow = X + (size_t)(m0 + lrow) * INP + lk4;
    const float* Brow = W + (size_t)(n0 + lrow) * INP + lk4;

    for (int k0 = 0; k0 < INP; k0 += 8) {
        float4 av = *reinterpret_cast<const float4*>(Arow + k0);
        float4 bv = *reinterpret_cast<const float4*>(Brow + k0);
        __syncthreads();
        As[lk4 + 0][lrow] = av.x; As[lk4 + 1][lrow] = av.y;
        As[lk4 + 2][lrow] = av.z; As[lk4 + 3][lrow] = av.w;
        Bs[lk4 + 0][lrow] = bv.x; Bs[lk4 + 1][lrow] = bv.y;
        Bs[lk4 + 2][lrow] = bv.z; Bs[lk4 + 3][lrow] = bv.w;
        __syncthreads();

#pragma unroll
        for (int kk = 0; kk < 8; kk++) {
            float4 a0 = *reinterpret_cast<const float4*>(&As[kk][ty * 8]);
            float4 a1 = *reinterpret_cast<const float4*>(&As[kk][ty * 8 + 4]);
            float4 b0 = *reinterpret_cast<const float4*>(&Bs[kk][tx * 8]);
            float4 b1 = *reinterpret_cast<const float4*>(&Bs[kk][tx * 8 + 4]);
            ull B4[4] = {pk2(b0.x, b0.y), pk2(b0.z, b0.w),
                         pk2(b1.x, b1.y), pk2(b1.z, b1.w)};
            float a[8] = {a0.x, a0.y, a0.z, a0.w, a1.x, a1.y, a1.z, a1.w};
#pragma unroll
            for (int i = 0; i < 8; i++) {
                ull ad = dup2(a[i]);
#pragma unroll
                for (int jp = 0; jp < 4; jp++) fma2(acc2[i][jp], ad, B4[jp]);
            }
        }
    }

    float bias[8];
#pragma unroll
    for (int j = 0; j < 8; j++) {
        int n = n0 + tx * 8 + j;
        bias[j] = b_ih[n] + b_hh[n];
    }

#pragma unroll
    for (int i = 0; i < 8; i++) {
        size_t row = (size_t)(m0 + ty * 8 + i);
        float* dst = &g_G[row * GATES + n0 + tx * 8];
#pragma unroll
        for (int jp = 0; jp < 4; jp++) {
            float2 v = up2(acc2[i][jp]);
            dst[2 * jp]     = v.x + bias[2 * jp];
            dst[2 * jp + 1] = v.y + bias[2 * jp + 1];
        }
    }
}

// ---------------------------------------------------------------------------
// Kernel 2: persistent reverse-LSTM recurrence, warp-specialized.
// Block bid owns hidden cols j in [bid*8, bid*8+8) -> 32 gate columns.
// Warps 0..7  : consumers (LDS + FFMA2), warp p has K-slice [p*128, p*128+128)
// Warps 8..15 : producers (LDG h -> transposed STS), warp 8+p feeds pair p
// Sync: named barrier (1+p, 64 threads) per 16-k chunk, double-buffered.
//
// Smem: Wt[1024][32]                (128 KB, staged once, reused 512 steps)
//       bufs[8 pairs][2][16k x 64b] (64 KB) -> overlaid as partials P[8][32][64]
// ---------------------------------------------------------------------------
__global__ __launch_bounds__(NTHR) void lstm_persistent(
    const float* __restrict__ W_hh,
    float* __restrict__ ys,
    float* __restrict__ hout,
    float* __restrict__ cout)
{
    extern __shared__ float smem[];
    float* Wt   = smem;            // 32768 floats
    float* bufs = smem + 32768;    // 16384 floats

    const int tid  = threadIdx.x;
    const int wid  = tid >> 5;
    const int lane = tid & 31;
    const int bid  = blockIdx.x;
    const int j0   = bid * 8;

    // --- one-time: stage W_hh rows (transposed to [k][n]) ---
    for (int i = tid; i < 32 * 1024; i += NTHR) {
        int n = i >> 10, k = i & 1023;           // consecutive tid -> consecutive k
        int l = n >> 3, jj = n & 7;
        Wt[k * 32 + n] = W_hh[(size_t)(l * HID + j0 + jj) * HID + k];
    }

    const ull gen0 = *(volatile ull*)&g_bar_gen;
    __syncthreads();

    const int pair  = wid & 7;
    const bool prod = (wid >= 8);
    const int kbase = pair * 128;
    float* buf0 = bufs + pair * 2048;
    float* buf1 = buf0 + 1024;

    // consumer micro-tile mapping: 8b x 8n
    const int b0 = (lane >> 2) * 8;
    const int n0 = (lane & 3) * 8;
    // producer staging mapping
    const int bq = lane >> 2, kq = (lane & 3) * 4;

    // cell mapping: exactly 1 cell per thread
    const int cb  = tid >> 3;       // 0..63
    const int cjj = tid & 7;        // 0..7
    float cst = 0.0f;

    ull nbar = 0;

    for (int t = T_STEPS - 1; t >= 0; --t) {
        const bool first = (t == T_STEPS - 1);

        if (!first) {
            if (prod) {
                // ---- producer: stream h (step t+1) into the double buffer ----
                const float* hp = ys + (size_t)(t + 1) * (BATCH * HID)
                                + kbase + kq + (size_t)bq * HID;
#pragma unroll 1
                for (int ch = 0; ch < 8; ch++) {
                    float4 ld[8];
#pragma unroll
                    for (int r = 0; r < 8; r++)
                        ld[r] = *reinterpret_cast<const float4*>(
                            hp + ch * 16 + (size_t)r * 8 * HID);
                    float* dst = (ch & 1) ? buf1 : buf0;
#pragma unroll
                    for (int r = 0; r < 8; r++) {
                        int b = r * 8 + bq;
                        dst[(kq + 0) * 64 + b] = ld[r].x;
                        dst[(kq + 1) * 64 + b] = ld[r].y;
                        dst[(kq + 2) * 64 + b] = ld[r].z;
                        dst[(kq + 3) * 64 + b] = ld[r].w;
                    }
                    BAR_SYNC_64(1 + pair);   // chunk ch ready
                }
            } else {
                // ---- consumer: dense LDS + FFMA2 ----
                ull acc2[4][8];
#pragma unroll
                for (int p = 0; p < 4; p++)
#pragma unroll
                    for (int n = 0; n < 8; n++) acc2[p][n] = 0ULL;

#pragma unroll 1
                for (int ch = 0; ch < 8; ch++) {
                    BAR_SYNC_64(1 + pair);   // wait chunk ch
                    float* cur = (ch & 1) ? buf1 : buf0;
#pragma unroll
                    for (int kk = 0; kk < 16; kk++) {
                        const int kg = kbase + ch * 16 + kk;
                        float4 a01 = *reinterpret_cast<const float4*>(&cur[kk * 64 + b0]);
                        float4 a23 = *reinterpret_cast<const float4*>(&cur[kk * 64 + b0 + 4]);
                        float4 w03 = *reinterpret_cast<const float4*>(&Wt[kg * 32 + n0]);
                        float4 w47 = *reinterpret_cast<const float4*>(&Wt[kg * 32 + n0 + 4]);
                        ull A[4] = {pk2(a01.x, a01.y), pk2(a01.z, a01.w),
                                    pk2(a23.x, a23.y), pk2(a23.z, a23.w)};
                        ull W8[8] = {dup2(w03.x), dup2(w03.y), dup2(w03.z), dup2(w03.w),
                                     dup2(w47.x), dup2(w47.y), dup2(w47.z), dup2(w47.w)};
#pragma unroll
                        for (int p = 0; p < 4; p++)
#pragma unroll
                            for (int n = 0; n < 8; n++) fma2(acc2[p][n], A[p], W8[n]);
                    }
                }

                // write partials, swizzled column (b + 2n) & 63 for conflict-free
                // column-major reads in the cell phase
                float* P = bufs + pair * 2048;
#pragma unroll
                for (int p = 0; p < 4; p++)
#pragma unroll
                    for (int n = 0; n < 8; n++) {
                        int ng  = n0 + n;
                        int col = (b0 + 2 * p + 2 * ng) & 63;
                        float2 v = up2(acc2[p][n]);
                        *reinterpret_cast<float2*>(&P[ng * 64 + col]) = v;
                    }
            }
        }
        __syncthreads();   // partials visible to all 16 warps

        // ---- block-local LSTM cell: 1 cell per thread ----
        {
            const float* Gt = g_G + ((size_t)t * BATCH + cb) * GATES + j0;
            float gv[4];
#pragma unroll
            for (int l = 0; l < 4; l++) {
                float s = Gt[l * HID + cjj];
                if (!first) {
                    int ng  = l * 8 + cjj;
                    int col = (cb + 2 * ng) & 63;
#pragma unroll
                    for (int w = 0; w < 8; w++)
                        s += bufs[w * 2048 + ng * 64 + col];
                }
                gv[l] = s;
            }
            float ig = sigf(gv[0]), fg = sigf(gv[1]);
            float gg = tanhf(gv[2]), og = sigf(gv[3]);
            cst = first ? (ig * gg) : (fg * cst + ig * gg);
            float h = og * tanhf(cst);

            ys[(size_t)t * (BATCH * HID) + (size_t)cb * HID + j0 + cjj] = h;
            if (t == 0) {
                hout[(size_t)cb * HID + j0 + cjj] = h;
                cout[(size_t)cb * HID + j0 + cjj] = cst;
            }
        }

        // ---- grid barrier (h of step t must be visible before step t-1) ----
        if (t > 0) {
            __threadfence();
            __syncthreads();
            if (tid == 0) {
                nbar++;
                unsigned prev = atomicAdd(&g_bar_cnt, 1u);
                if (prev == (unsigned)(gridDim.x - 1)) {
                    atomicExch(&g_bar_cnt, 0u);
                    __threadfence();
                    atomicAdd(&g_bar_gen, 1ULL);
                } else {
                    while (*(volatile ull*)&g_bar_gen < gen0 + nbar) {
                        __nanosleep(32);
                    }
                }
                __threadfence();
            }
            __syncthreads();
        }
    }
}

// ---------------------------------------------------------------------------
extern "C" void kernel_launch(void* const* d_in, const int* in_sizes, int n_in,
                              void* d_out, int out_size)
{
    const float* x    = (const float*)d_in[0];
    const float* w_ih = (const float*)d_in[1];
    const float* w_hh = (const float*)d_in[2];
    const float* b_ih = (const float*)d_in[3];
    const float* b_hh = (const float*)d_in[4];

    float* out  = (float*)d_out;
    float* ys   = out;                                  // (T, B, H)
    float* hout = out + (size_t)T_STEPS * BATCH * HID;  // (1, B, H)
    float* cout = hout + (size_t)BATCH * HID;           // (1, B, H)

    const int smem_bytes = (32768 + 16384) * sizeof(float);  // 192 KB
    cudaFuncSetAttribute(lstm_persistent,
                         cudaFuncAttributeMaxDynamicSharedMemorySize, smem_bytes);

    // Node 1: all input projections (parallel over T)
    input_gemm_kernel<<<dim3(GATES / 128, (T_STEPS * BATCH) / 128), 256>>>(
        x, w_ih, b_ih, b_hh);

    // Node 2: entire reverse-time recurrence in one persistent kernel
    lstm_persistent<<<NBLK, NTHR, smem_bytes>>>(w_hh, ys, hout, cout);
}

// round 8
// speedup vs baseline: 1.3852x; 1.3852x over previous
#include <cuda_runtime.h>
#include <math.h>
#include <stdint.h>

typedef unsigned long long ull;

#define T_STEPS 512
#define BATCH   64
#define INP     1024
#define HID     1024
#define GATES   4096
#define NBLK    128
#define NTHR    256

// Static scratch (no allocation APIs allowed)
__device__ __align__(16) float g_G [(size_t)T_STEPS * BATCH * GATES];  // 512 MB
__device__ __align__(16) float g_xt[(size_t)T_STEPS * BATCH * INP];    // 128 MB (tf32-rounded x)
__device__ __align__(16) float g_wt[(size_t)GATES * INP];              // 16 MB  (tf32-rounded W_ih)
__device__ ull       g_bar_gen;
__device__ unsigned  g_bar_cnt;

// ---- packed fp32x2 helpers ----
__device__ __forceinline__ ull pk2(float x, float y) {
    ull r; asm("mov.b64 %0, {%1, %2};" : "=l"(r) : "f"(x), "f"(y)); return r;
}
__device__ __forceinline__ ull dup2(float x) {
    ull r; asm("mov.b64 %0, {%1, %1};" : "=l"(r) : "f"(x)); return r;
}
__device__ __forceinline__ void fma2(ull& d, ull a, ull b) {
    asm("fma.rn.f32x2 %0, %1, %2, %0;" : "+l"(d) : "l"(a), "l"(b));
}
__device__ __forceinline__ float2 up2(ull v) {
    float2 f; asm("mov.b64 {%0, %1}, %2;" : "=f"(f.x), "=f"(f.y) : "l"(v)); return f;
}
__device__ __forceinline__ float sigf(float v) { return 1.0f / (1.0f + expf(-v)); }

// canonical b32-destination form of the tf32 round
__device__ __forceinline__ float tf32r(float x) {
    uint32_t r; asm("cvt.rna.tf32.f32 %0, %1;" : "=r"(r) : "f"(x));
    return __uint_as_float(r);
}

__device__ __forceinline__ void mma_tf32(
    float& d0, float& d1, float& d2, float& d3,
    uint32_t a0, uint32_t a1, uint32_t a2, uint32_t a3,
    uint32_t b0, uint32_t b1)
{
    asm volatile(
        "mma.sync.aligned.m16n8k8.row.col.f32.tf32.tf32.f32 "
        "{%0,%1,%2,%3}, {%4,%5,%6,%7}, {%8,%9}, {%0,%1,%2,%3};"
        : "+f"(d0), "+f"(d1), "+f"(d2), "+f"(d3)
        : "r"(a0), "r"(a1), "r"(a2), "r"(a3), "r"(b0), "r"(b1));
}

// ---------------------------------------------------------------------------
// Kernel 0: round fp32 -> tf32 values (grid-stride over float4)
// ---------------------------------------------------------------------------
__global__ void cvt_tf32_kernel(const float4* __restrict__ in,
                                float4* __restrict__ out, int n4)
{
    for (int i = blockIdx.x * blockDim.x + threadIdx.x; i < n4;
         i += gridDim.x * blockDim.x) {
        float4 v = in[i];
        v.x = tf32r(v.x); v.y = tf32r(v.y);
        v.z = tf32r(v.z); v.w = tf32r(v.w);
        out[i] = v;
    }
}

// ---------------------------------------------------------------------------
// Kernel 1: G = X @ W_ih^T + bias, tf32 tensor cores (mma.sync m16n8k8).
// M = 32768, N = 4096, K = 1024. Block 128x128, BK=16, 256 thr,
// warp tile 64m x 32n (warps 2m x 4n), 16 mma per k8-step.
// ---------------------------------------------------------------------------
__global__ __launch_bounds__(256) void input_gemm_tf32(
    const float* __restrict__ b_ih,
    const float* __restrict__ b_hh)
{
    __shared__ __align__(16) float As[128][20];   // [m][k], pad 20
    __shared__ __align__(16) float Bs[16][136];   // [k][n], pad 136

    const int tid  = threadIdx.x;
    const int lane = tid & 31;
    const int wid  = tid >> 5;
    const int n0   = blockIdx.x * 128;
    const int m0   = blockIdx.y * 128;
    const int wm   = ((wid >> 2) & 1) * 64;
    const int wn   = (wid & 3) * 32;
    const int gid  = lane >> 2;     // 0..7
    const int tig  = lane & 3;      // 0..3

    float acc[4][4][4];
#pragma unroll
    for (int mt = 0; mt < 4; mt++)
#pragma unroll
        for (int nt = 0; nt < 4; nt++)
#pragma unroll
            for (int r = 0; r < 4; r++) acc[mt][nt][r] = 0.0f;

    // bias pairs for this lane's output columns
    float bias0[4], bias1[4];
#pragma unroll
    for (int nt = 0; nt < 4; nt++) {
        int col = n0 + wn + nt * 8 + 2 * tig;
        bias0[nt] = b_ih[col] + b_hh[col];
        bias1[nt] = b_ih[col + 1] + b_hh[col + 1];
    }

    const int arow = tid >> 1, akq = tid & 1;
    const float4* asrc = reinterpret_cast<const float4*>(
        g_xt + (size_t)(m0 + arow) * INP + akq * 8);
    const float4* bsrc = reinterpret_cast<const float4*>(
        g_wt + (size_t)(n0 + arow) * INP + akq * 8);

    for (int k0 = 0; k0 < INP; k0 += 16) {
        // stage A [128m x 16k] straight, B [16k x 128n] transposed
        float4 a0 = asrc[k0 / 4];
        float4 a1 = asrc[k0 / 4 + 1];
        float4 w0 = bsrc[k0 / 4];
        float4 w1 = bsrc[k0 / 4 + 1];
        __syncthreads();
        *reinterpret_cast<float4*>(&As[arow][akq * 8])     = a0;
        *reinterpret_cast<float4*>(&As[arow][akq * 8 + 4]) = a1;
        {
            int kb = akq * 8, nn = arow;
            Bs[kb + 0][nn] = w0.x; Bs[kb + 1][nn] = w0.y;
            Bs[kb + 2][nn] = w0.z; Bs[kb + 3][nn] = w0.w;
            Bs[kb + 4][nn] = w1.x; Bs[kb + 5][nn] = w1.y;
            Bs[kb + 6][nn] = w1.z; Bs[kb + 7][nn] = w1.w;
        }
        __syncthreads();

#pragma unroll
        for (int ks = 0; ks < 16; ks += 8) {
            uint32_t a[4][4];
#pragma unroll
            for (int mt = 0; mt < 4; mt++) {
                int r = wm + mt * 16 + gid;
                a[mt][0] = __float_as_uint(As[r][ks + tig]);
                a[mt][1] = __float_as_uint(As[r + 8][ks + tig]);
                a[mt][2] = __float_as_uint(As[r][ks + tig + 4]);
                a[mt][3] = __float_as_uint(As[r + 8][ks + tig + 4]);
            }
            uint32_t b[4][2];
#pragma unroll
            for (int nt = 0; nt < 4; nt++) {
                int c = wn + nt * 8 + gid;
                b[nt][0] = __float_as_uint(Bs[ks + tig][c]);
                b[nt][1] = __float_as_uint(Bs[ks + tig + 4][c]);
            }
#pragma unroll
            for (int mt = 0; mt < 4; mt++)
#pragma unroll
                for (int nt = 0; nt < 4; nt++)
                    mma_tf32(acc[mt][nt][0], acc[mt][nt][1],
                             acc[mt][nt][2], acc[mt][nt][3],
                             a[mt][0], a[mt][1], a[mt][2], a[mt][3],
                             b[nt][0], b[nt][1]);
        }
    }

    // epilogue: add bias, write pairs
#pragma unroll
    for (int mt = 0; mt < 4; mt++) {
        size_t r0 = (size_t)(m0 + wm + mt * 16 + gid);
#pragma unroll
        for (int nt = 0; nt < 4; nt++) {
            int col = n0 + wn + nt * 8 + 2 * tig;
            *reinterpret_cast<float2*>(&g_G[r0 * GATES + col]) =
                make_float2(acc[mt][nt][0] + bias0[nt], acc[mt][nt][1] + bias1[nt]);
            *reinterpret_cast<float2*>(&g_G[(r0 + 8) * GATES + col]) =
                make_float2(acc[mt][nt][2] + bias0[nt], acc[mt][nt][3] + bias1[nt]);
        }
    }
}

// ---------------------------------------------------------------------------
// Kernel 2: persistent reverse-LSTM recurrence (R4 structure, measured best) +
// swizzled partials (R6-validated). 256 thr, 8 warps, K-slice 128/warp.
// ---------------------------------------------------------------------------
__global__ __launch_bounds__(NTHR, 1) void lstm_persistent(
    const float* __restrict__ W_hh,
    float* __restrict__ ys,
    float* __restrict__ hout,
    float* __restrict__ cout)
{
    extern __shared__ float smem[];
    float* Wt   = smem;            // 32768 floats
    float* bufs = smem + 32768;    // 16384 floats

    const int tid  = threadIdx.x;
    const int wid  = tid >> 5;
    const int lane = tid & 31;
    const int bid  = blockIdx.x;
    const int j0   = bid * 8;

    for (int i = tid; i < 32 * 1024; i += NTHR) {
        int n = i >> 10, k = i & 1023;
        int l = n >> 3, jj = n & 7;
        Wt[k * 32 + n] = W_hh[(size_t)(l * HID + j0 + jj) * HID + k];
    }

    const ull gen0 = *(volatile ull*)&g_bar_gen;
    __syncthreads();

    const int b0 = (lane >> 2) * 8;
    const int n0 = (lane & 3) * 8;
    const int kbase = wid * 128;
    float* buf0 = bufs + wid * 2048;
    float* buf1 = buf0 + 1024;

    const int cb  = tid >> 2;
    const int cjj = (tid & 3) * 2;
    float cst0 = 0.0f, cst1 = 0.0f;

    ull nbar = 0;

    for (int t = T_STEPS - 1; t >= 0; --t) {
        const bool first = (t == T_STEPS - 1);

        if (!first) {
            const float* h = ys + (size_t)(t + 1) * (BATCH * HID);
            const float* hp = h + kbase + (lane & 3) * 4 + (size_t)(lane >> 2) * HID;

            ull acc2[4][8];
#pragma unroll
            for (int p = 0; p < 4; p++)
#pragma unroll
                for (int n = 0; n < 8; n++) acc2[p][n] = 0ULL;

            float4 ld[8];
#pragma unroll
            for (int r = 0; r < 8; r++)
                ld[r] = *reinterpret_cast<const float4*>(hp + (size_t)r * 8 * HID);
            {
                const int bq = lane >> 2, kq = (lane & 3) * 4;
#pragma unroll
                for (int r = 0; r < 8; r++) {
                    int b = r * 8 + bq;
                    buf0[(kq + 0) * 64 + b] = ld[r].x;
                    buf0[(kq + 1) * 64 + b] = ld[r].y;
                    buf0[(kq + 2) * 64 + b] = ld[r].z;
                    buf0[(kq + 3) * 64 + b] = ld[r].w;
                }
            }
            __syncwarp();

            for (int ch = 0; ch < 8; ch++) {
                float* cur = (ch & 1) ? buf1 : buf0;
                if (ch < 7) {
#pragma unroll
                    for (int r = 0; r < 8; r++)
                        ld[r] = *reinterpret_cast<const float4*>(
                            hp + (ch + 1) * 16 + (size_t)r * 8 * HID);
                }
#pragma unroll
                for (int kk = 0; kk < 16; kk++) {
                    const int kg = kbase + ch * 16 + kk;
                    float4 a01 = *reinterpret_cast<const float4*>(&cur[kk * 64 + b0]);
                    float4 a23 = *reinterpret_cast<const float4*>(&cur[kk * 64 + b0 + 4]);
                    float4 w03 = *reinterpret_cast<const float4*>(&Wt[kg * 32 + n0]);
                    float4 w47 = *reinterpret_cast<const float4*>(&Wt[kg * 32 + n0 + 4]);
                    ull A[4] = {pk2(a01.x, a01.y), pk2(a01.z, a01.w),
                                pk2(a23.x, a23.y), pk2(a23.z, a23.w)};
                    ull W8[8] = {dup2(w03.x), dup2(w03.y), dup2(w03.z), dup2(w03.w),
                                 dup2(w47.x), dup2(w47.y), dup2(w47.z), dup2(w47.w)};
#pragma unroll
                    for (int p = 0; p < 4; p++)
#pragma unroll
                        for (int n = 0; n < 8; n++) fma2(acc2[p][n], A[p], W8[n]);
                }
                if (ch < 7) {
                    float* nxt = (ch & 1) ? buf0 : buf1;
                    __syncwarp();
                    const int bq = lane >> 2, kq = (lane & 3) * 4;
#pragma unroll
                    for (int r = 0; r < 8; r++) {
                        int b = r * 8 + bq;
                        nxt[(kq + 0) * 64 + b] = ld[r].x;
                        nxt[(kq + 1) * 64 + b] = ld[r].y;
                        nxt[(kq + 2) * 64 + b] = ld[r].z;
                        nxt[(kq + 3) * 64 + b] = ld[r].w;
                    }
                    __syncwarp();
                }
            }

            // swizzled partials: batch b -> column (b + 2*ng) & 63
            __syncwarp();
            float* P = bufs + wid * 2048;
#pragma unroll
            for (int p = 0; p < 4; p++)
#pragma unroll
                for (int n = 0; n < 8; n++) {
                    int ng  = n0 + n;
                    int col = (b0 + 2 * p + 2 * ng) & 63;
                    float2 v = up2(acc2[p][n]);
                    *reinterpret_cast<float2*>(&P[ng * 64 + col]) = v;
                }
        }
        __syncthreads();

        // ---- cell: 2 cells per thread ----
        {
            const float* Gt = g_G + ((size_t)t * BATCH + cb) * GATES + j0;
            float gv0[4], gv1[4];
#pragma unroll
            for (int l = 0; l < 4; l++) {
                float sA = Gt[l * HID + cjj];
                float sB = Gt[l * HID + cjj + 1];
                if (!first) {
                    int ngA = l * 8 + cjj;
                    int colA = (cb + 2 * ngA) & 63;
                    int colB = (cb + 2 * (ngA + 1)) & 63;
#pragma unroll
                    for (int w = 0; w < 8; w++) {
                        sA += bufs[w * 2048 + ngA * 64 + colA];
                        sB += bufs[w * 2048 + (ngA + 1) * 64 + colB];
                    }
                }
                gv0[l] = sA; gv1[l] = sB;
            }
            float i0 = sigf(gv0[0]), f0 = sigf(gv0[1]), gg0 = tanhf(gv0[2]), o0 = sigf(gv0[3]);
            float i1 = sigf(gv1[0]), f1 = sigf(gv1[1]), gg1 = tanhf(gv1[2]), o1 = sigf(gv1[3]);
            cst0 = first ? (i0 * gg0) : (f0 * cst0 + i0 * gg0);
            cst1 = first ? (i1 * gg1) : (f1 * cst1 + i1 * gg1);
            float h0 = o0 * tanhf(cst0);
            float h1 = o1 * tanhf(cst1);

            float2 hv = make_float2(h0, h1);
            *reinterpret_cast<float2*>(
                &ys[(size_t)t * (BATCH * HID) + (size_t)cb * HID + j0 + cjj]) = hv;
            if (t == 0) {
                *reinterpret_cast<float2*>(&hout[(size_t)cb * HID + j0 + cjj]) = hv;
                *reinterpret_cast<float2*>(&cout[(size_t)cb * HID + j0 + cjj]) =
                    make_float2(cst0, cst1);
            }
        }

        if (t > 0) {
            __threadfence();
            __syncthreads();
            if (tid == 0) {
                nbar++;
                unsigned prev = atomicAdd(&g_bar_cnt, 1u);
                if (prev == (unsigned)(gridDim.x - 1)) {
                    atomicExch(&g_bar_cnt, 0u);
                    __threadfence();
                    atomicAdd(&g_bar_gen, 1ULL);
                } else {
                    while (*(volatile ull*)&g_bar_gen < gen0 + nbar) {
                        __nanosleep(32);
                    }
                }
                __threadfence();
            }
            __syncthreads();
        }
    }
}

// ---------------------------------------------------------------------------
extern "C" void kernel_launch(void* const* d_in, const int* in_sizes, int n_in,
                              void* d_out, int out_size)
{
    const float* x    = (const float*)d_in[0];
    const float* w_ih = (const float*)d_in[1];
    const float* w_hh = (const float*)d_in[2];
    const float* b_ih = (const float*)d_in[3];
    const float* b_hh = (const float*)d_in[4];

    float* out  = (float*)d_out;
    float* ys   = out;
    float* hout = out + (size_t)T_STEPS * BATCH * HID;
    float* cout = hout + (size_t)BATCH * HID;

    const int smem_bytes = (32768 + 16384) * sizeof(float);  // 192 KB
    cudaFuncSetAttribute(lstm_persistent,
                         cudaFuncAttributeMaxDynamicSharedMemorySize, smem_bytes);

    // resolve device scratch addresses (pure query — no allocation, capture-safe)
    float *xt_p, *wt_p;
    cudaGetSymbolAddress((void**)&xt_p, g_xt);
    cudaGetSymbolAddress((void**)&wt_p, g_wt);

    // Node 0a/0b: tf32-round x and W_ih
    cvt_tf32_kernel<<<4096, 256>>>(
        (const float4*)x, (float4*)xt_p, (T_STEPS * BATCH * INP) / 4);
    cvt_tf32_kernel<<<1024, 256>>>(
        (const float4*)w_ih, (float4*)wt_p, (GATES * INP) / 4);

    // Node 1: input projection via tf32 tensor cores
    input_gemm_tf32<<<dim3(GATES / 128, (T_STEPS * BATCH) / 128), 256>>>(
        b_ih, b_hh);

    // Node 2: persistent recurrence
    lstm_persistent<<<NBLK, NTHR, smem_bytes>>>(w_hh, ys, hout, cout);
}